// round 2
// baseline (speedup 1.0000x reference)
#include <cuda_runtime.h>
#include <math.h>

// ---------------------------------------------------------------------------
// Problem constants
// ---------------------------------------------------------------------------
#define BG   2048      // graphs
#define NN_  65536     // nodes
#define NE_  131072    // edges
#define DN_  256       // node dim
#define DE_  128       // edge dim

// ---------------------------------------------------------------------------
// Scratch (device globals; allocation-free)
// ---------------------------------------------------------------------------
__device__ float g_h_n[BG * DN_];
__device__ float g_c_n[BG * DN_];
__device__ float g_qstar_n[BG * 2 * DN_];
__device__ float g_gates_n[BG * 4 * DN_];

__device__ float g_h_e[BG * DE_];
__device__ float g_c_e[BG * DE_];
__device__ float g_qstar_e[BG * 2 * DE_];
__device__ float g_gates_e[BG * 4 * DE_];

__device__ float g_Wcomb_n[4 * DN_ * 2 * DN_];   // [1024, 512]
__device__ float g_Wcomb_e[4 * DE_ * 2 * DE_];   // [512, 256]

__device__ float g_score[NE_];          // reused for node (N<=E) and edge phases
__device__ float g_qcat[BG * 768];
__device__ float g_t1[BG * 512];
__device__ float g_t2[BG * 2048];
__device__ float g_t3[BG * 512];
__device__ float g_t4[BG * 512];
__device__ int   g_off_n[BG + 1];
__device__ int   g_off_e[BG + 1];

// ---------------------------------------------------------------------------
// Utility kernels
// ---------------------------------------------------------------------------
__global__ void zero_state_kernel() {
    int i = blockIdx.x * 256 + threadIdx.x;
    if (i < BG * 2 * DN_) g_qstar_n[i] = 0.f;          // 1048576 elems
    if (i < BG * DN_)     { g_h_n[i] = 0.f; g_c_n[i] = 0.f; }
    if (i < BG * 2 * DE_) g_qstar_e[i] = 0.f;
    if (i < BG * DE_)     { g_h_e[i] = 0.f; g_c_e[i] = 0.f; }
}

// Wcomb[r, c] = Wih[r, c] + (c < D ? Whh[r, c] : 0).  Wih: [4D, 2D], Whh: [4D, D]
__global__ void wcomb_kernel(const float* __restrict__ Wih,
                             const float* __restrict__ Whh,
                             float* __restrict__ Wcomb, int D) {
    int i = blockIdx.x * 256 + threadIdx.x;
    int total = 4 * D * 2 * D;
    if (i >= total) return;
    int r = i / (2 * D), c = i - r * 2 * D;
    float v = Wih[i];
    if (c < D) v += Whh[(size_t)r * D + c];
    Wcomb[i] = v;
}

// iter-0 gates: gates[b, j] = bih[j] + bhh[j]
__global__ void gates_bias_kernel(const float* __restrict__ bih,
                                  const float* __restrict__ bhh,
                                  float* __restrict__ gates, int G) {
    int i = blockIdx.x * 256 + threadIdx.x;
    if (i >= BG * G) return;
    int j = i % G;
    gates[i] = bih[j] + bhh[j];
}

// segment offsets via lower_bound on sorted seg array
__global__ void segoff_kernel(const int* __restrict__ seg, int M, int* __restrict__ off) {
    int b = blockIdx.x * blockDim.x + threadIdx.x;
    if (b > BG) return;
    int lo = 0, hi = M;
    while (lo < hi) {
        int mid = (lo + hi) >> 1;
        if (seg[mid] < b) lo = mid + 1; else hi = mid;
    }
    off[b] = lo;
}

__device__ __forceinline__ float sigmoidf_(float x) {
    return 1.f / (1.f + expf(-x));
}

// LSTM pointwise: gates [B,4D] -> update h,c, write q into qstar[:, :D]
__global__ void lstm_pw_kernel(const float* __restrict__ gates,
                               float* __restrict__ h, float* __restrict__ c,
                               float* __restrict__ qstar, int D) {
    int idx = blockIdx.x * 256 + threadIdx.x;
    if (idx >= BG * D) return;
    int b = idx / D, d = idx - b * D;
    const float* gr = gates + (size_t)b * 4 * D;
    float gi = gr[d];
    float gf = gr[D + d];
    float gg = gr[2 * D + d];
    float go = gr[3 * D + d];
    float cn = sigmoidf_(gf) * c[idx] + sigmoidf_(gi) * tanhf(gg);
    float hn = sigmoidf_(go) * tanhf(cn);
    c[idx] = cn;
    h[idx] = hn;
    qstar[(size_t)b * 2 * D + d] = hn;
}

// ---------------------------------------------------------------------------
// Set2Set attention: one block per segment, 2 passes over feat rows.
// readout = sum(w_m * feat_m) / sum(w_m), w_m = exp(score_m - max)
// ---------------------------------------------------------------------------
template <int D>
__global__ __launch_bounds__(256) void s2s_attn_kernel(
    const float* __restrict__ feat, const int* __restrict__ segoff,
    const float* __restrict__ h, float* __restrict__ qstar,
    float* __restrict__ scorebuf) {
    int b = blockIdx.x;
    int tid = threadIdx.x, lane = tid & 31, w = tid >> 5;
    int start = segoff[b], end = segoff[b + 1];

    __shared__ float q[D];
    __shared__ float acc[8][D];
    __shared__ float red[8];

    for (int i = tid; i < D; i += 256) q[i] = h[(size_t)b * D + i];
    for (int i = tid; i < 8 * D; i += 256) (&acc[0][0])[i] = 0.f;
    __syncthreads();

    // Pass 1: scores + max (warp per row)
    float wmax = -INFINITY;
    for (int m = start + w; m < end; m += 8) {
        const float* fr = feat + (size_t)m * D;
        float s = 0.f;
        #pragma unroll
        for (int k = lane; k < D; k += 32) s += fr[k] * q[k];
        #pragma unroll
        for (int o = 16; o; o >>= 1) s += __shfl_xor_sync(0xffffffffu, s, o);
        if (lane == 0) scorebuf[m] = s;
        wmax = fmaxf(wmax, s);
    }
    if (lane == 0) red[w] = wmax;
    __syncthreads();
    float smax = -INFINITY;
    #pragma unroll
    for (int i = 0; i < 8; i++) smax = fmaxf(smax, red[i]);
    __syncthreads();   // red is reused below

    // Pass 2: weighted accumulation
    float sumw = 0.f;
    for (int m = start + w; m < end; m += 8) {
        const float* fr = feat + (size_t)m * D;
        float wv = expf(scorebuf[m] - smax);
        if (lane == 0) sumw += wv;
        #pragma unroll
        for (int k = lane; k < D; k += 32) acc[w][k] += wv * fr[k];
    }
    if (lane == 0) red[w] = sumw;
    __syncthreads();
    float tot = 0.f;
    #pragma unroll
    for (int i = 0; i < 8; i++) tot += red[i];
    float inv = (tot > 0.f) ? (1.f / tot) : 0.f;

    for (int k = tid; k < D; k += 256) {
        float r = 0.f;
        #pragma unroll
        for (int i = 0; i < 8; i++) r += acc[i][k];
        qstar[(size_t)b * 2 * D + D + k] = r * inv;
    }
}

// ---------------------------------------------------------------------------
// SIMT fp32 GEMM: C[M,N] = op( A[M,K] * W + bias ), optional accumulate.
//  TRANSB=1: W is [N,K] row-major (use W^T)    -> LSTM weights
//  TRANSB=0: W is [K,N] row-major              -> MLP weights
//  BIASMODE: 0 none, 1 bias1, 2 bias1+bias2
//  BETA: 1 -> C += result ; ACT: 1 -> relu
// BM=128, BN=64, BK=16, 256 threads, 8x4 per-thread tile.
// Requires M%128==0, N%64==0, K%16==0.
// ---------------------------------------------------------------------------
template <int TRANSB, int ACT, int BETA, int BIASMODE>
__global__ __launch_bounds__(256) void gemm_kernel(
    const float* __restrict__ A, const float* __restrict__ W,
    const float* __restrict__ bias1, const float* __restrict__ bias2,
    float* __restrict__ C, int M, int N, int K) {
    __shared__ float As[16][128];
    __shared__ float Bs[16][64];

    int tid = threadIdx.x;
    int tx = tid & 15;        // 0..15 -> 4 cols each
    int ty = tid >> 4;        // 0..15 -> 8 rows each
    int row0 = blockIdx.y * 128;
    int col0 = blockIdx.x * 64;

    float acc[8][4];
    #pragma unroll
    for (int i = 0; i < 8; i++)
        #pragma unroll
        for (int j = 0; j < 4; j++) acc[i][j] = 0.f;

    for (int k0 = 0; k0 < K; k0 += 16) {
        // A tile: 128x16
        #pragma unroll
        for (int r = 0; r < 8; r++) {
            int t = tid + r * 256;
            int k = t & 15, m = t >> 4;
            As[k][m] = A[(size_t)(row0 + m) * K + k0 + k];
        }
        // B tile: 16x64
        if (TRANSB) {
            #pragma unroll
            for (int r = 0; r < 4; r++) {
                int t = tid + r * 256;
                int k = t & 15, n = t >> 4;
                Bs[k][n] = W[(size_t)(col0 + n) * K + k0 + k];
            }
        } else {
            #pragma unroll
            for (int r = 0; r < 4; r++) {
                int t = tid + r * 256;
                int n = t & 63, k = t >> 6;
                Bs[k][n] = W[(size_t)(k0 + k) * N + col0 + n];
            }
        }
        __syncthreads();
        #pragma unroll
        for (int kk = 0; kk < 16; kk++) {
            float av[8], bv[4];
            #pragma unroll
            for (int i = 0; i < 8; i++) av[i] = As[kk][ty * 8 + i];
            #pragma unroll
            for (int j = 0; j < 4; j++) bv[j] = Bs[kk][tx * 4 + j];
            #pragma unroll
            for (int i = 0; i < 8; i++)
                #pragma unroll
                for (int j = 0; j < 4; j++) acc[i][j] += av[i] * bv[j];
        }
        __syncthreads();
    }

    #pragma unroll
    for (int i = 0; i < 8; i++) {
        int r = row0 + ty * 8 + i;
        #pragma unroll
        for (int j = 0; j < 4; j++) {
            int cix = col0 + tx * 4 + j;
            float v = acc[i][j];
            if (BIASMODE == 1) v += bias1[cix];
            if (BIASMODE == 2) v += bias1[cix] + bias2[cix];
            float* cp = &C[(size_t)r * N + cix];
            if (BETA) v += *cp;
            if (ACT) v = fmaxf(v, 0.f);
            *cp = v;
        }
    }
}

// concat qstar_n (512) and qstar_e (256) -> qcat [B,768]
__global__ void concat_kernel() {
    int i = blockIdx.x * 256 + threadIdx.x;
    if (i >= BG * 768) return;
    int b = i / 768, j = i - b * 768;
    g_qcat[i] = (j < 512) ? g_qstar_n[(size_t)b * 512 + j]
                          : g_qstar_e[(size_t)b * 256 + (j - 512)];
}

// final GEMV: pred[b] = t4[b,:] . Wf3[:,0] + bf3  (K=512)
__global__ void gemv_final_kernel(const float* __restrict__ A,
                                  const float* __restrict__ w,
                                  const float* __restrict__ bias,
                                  float* __restrict__ out, int K) {
    int b = blockIdx.x * 8 + (threadIdx.x >> 5);
    int lane = threadIdx.x & 31;
    if (b >= BG) return;
    const float* ar = A + (size_t)b * K;
    float s = 0.f;
    for (int k = lane; k < K; k += 32) s += ar[k] * w[k];
    #pragma unroll
    for (int o = 16; o; o >>= 1) s += __shfl_xor_sync(0xffffffffu, s, o);
    if (lane == 0) out[b] = s + bias[0];
}

// ---------------------------------------------------------------------------
// Host orchestration
// ---------------------------------------------------------------------------
static float* fsym(const void* s) {
    void* p = nullptr;
    cudaGetSymbolAddress(&p, s);
    return (float*)p;
}
static int* isym(const void* s) {
    void* p = nullptr;
    cudaGetSymbolAddress(&p, s);
    return (int*)p;
}

extern "C" void kernel_launch(void* const* d_in, const int* in_sizes, int n_in,
                              void* d_out, int out_size) {
    const float* node_feat = (const float*)d_in[0];
    const float* edge_feat = (const float*)d_in[1];
    const int*   node_seg  = (const int*)d_in[2];
    const int*   edge_seg  = (const int*)d_in[3];
    const float* Wih_n = (const float*)d_in[4];
    const float* Whh_n = (const float*)d_in[5];
    const float* bih_n = (const float*)d_in[6];
    const float* bhh_n = (const float*)d_in[7];
    const float* Wih_e = (const float*)d_in[8];
    const float* Whh_e = (const float*)d_in[9];
    const float* bih_e = (const float*)d_in[10];
    const float* bhh_e = (const float*)d_in[11];
    const float* Wd1 = (const float*)d_in[12];
    const float* bd1 = (const float*)d_in[13];
    const float* Wd2 = (const float*)d_in[14];
    const float* bd2 = (const float*)d_in[15];
    const float* Wf1 = (const float*)d_in[16];
    const float* bf1 = (const float*)d_in[17];
    const float* Wf2 = (const float*)d_in[18];
    const float* bf2 = (const float*)d_in[19];
    const float* Wf3 = (const float*)d_in[20];
    const float* bf3 = (const float*)d_in[21];
    float* out = (float*)d_out;

    float* h_n = fsym(g_h_n);      float* c_n = fsym(g_c_n);
    float* qs_n = fsym(g_qstar_n); float* ga_n = fsym(g_gates_n);
    float* h_e = fsym(g_h_e);      float* c_e = fsym(g_c_e);
    float* qs_e = fsym(g_qstar_e); float* ga_e = fsym(g_gates_e);
    float* Wc_n = fsym(g_Wcomb_n); float* Wc_e = fsym(g_Wcomb_e);
    float* score = fsym(g_score);
    float* qcat = fsym(g_qcat);
    float* t1 = fsym(g_t1); float* t2 = fsym(g_t2);
    float* t3 = fsym(g_t3); float* t4 = fsym(g_t4);
    int* off_n = isym(g_off_n); int* off_e = isym(g_off_e);

    // init
    zero_state_kernel<<<(BG * 2 * DN_ + 255) / 256, 256>>>();
    segoff_kernel<<<(BG + 1 + 255) / 256, 256>>>(node_seg, NN_, off_n);
    segoff_kernel<<<(BG + 1 + 255) / 256, 256>>>(edge_seg, NE_, off_e);
    wcomb_kernel<<<(4 * DN_ * 2 * DN_ + 255) / 256, 256>>>(Wih_n, Whh_n, Wc_n, DN_);
    wcomb_kernel<<<(4 * DE_ * 2 * DE_ + 255) / 256, 256>>>(Wih_e, Whh_e, Wc_e, DE_);

    // ---- node Set2Set (D=256, HN=512, gates 4D=1024) ----
    {
        dim3 grid(1024 / 64, BG / 128);
        for (int it = 0; it < 6; it++) {
            if (it == 0) {
                gates_bias_kernel<<<(BG * 1024 + 255) / 256, 256>>>(bih_n, bhh_n, ga_n, 1024);
            } else {
                gemm_kernel<1, 0, 0, 2><<<grid, 256>>>(qs_n, Wc_n, bih_n, bhh_n,
                                                       ga_n, BG, 1024, 512);
            }
            lstm_pw_kernel<<<(BG * DN_ + 255) / 256, 256>>>(ga_n, h_n, c_n, qs_n, DN_);
            s2s_attn_kernel<DN_><<<BG, 256>>>(node_feat, off_n, h_n, qs_n, score);
        }
    }

    // ---- edge Set2Set (D=128, HE=256, gates 4D=512) ----
    {
        dim3 grid(512 / 64, BG / 128);
        for (int it = 0; it < 6; it++) {
            if (it == 0) {
                gates_bias_kernel<<<(BG * 512 + 255) / 256, 256>>>(bih_e, bhh_e, ga_e, 512);
            } else {
                gemm_kernel<1, 0, 0, 2><<<grid, 256>>>(qs_e, Wc_e, bih_e, bhh_e,
                                                       ga_e, BG, 512, 256);
            }
            lstm_pw_kernel<<<(BG * DE_ + 255) / 256, 256>>>(ga_e, h_e, c_e, qs_e, DE_);
            s2s_attn_kernel<DE_><<<BG, 256>>>(edge_feat, off_e, h_e, qs_e, score);
        }
    }

    // ---- decode + regression FFN ----
    concat_kernel<<<(BG * 768 + 255) / 256, 256>>>();
    {
        dim3 g1(512 / 64, BG / 128);
        gemm_kernel<0, 1, 0, 1><<<g1, 256>>>(qcat, Wd1, bd1, nullptr, t1, BG, 512, 768);
        dim3 g2(2048 / 64, BG / 128);
        gemm_kernel<0, 0, 0, 1><<<g2, 256>>>(t1, Wd2, bd2, nullptr, t2, BG, 2048, 512);
        gemm_kernel<0, 1, 0, 1><<<g1, 256>>>(t2, Wf1, bf1, nullptr, t3, BG, 512, 2048);
        gemm_kernel<0, 1, 0, 1><<<g1, 256>>>(t3, Wf2, bf2, nullptr, t4, BG, 512, 512);
    }
    gemv_final_kernel<<<BG / 8, 256>>>(t4, Wf3, bf3, out, 512);
}

// round 6
// speedup vs baseline: 2.3773x; 2.3773x over previous
#include <cuda_runtime.h>
#include <cuda_bf16.h>
#include <math.h>
#include <stdint.h>

// ---------------------------------------------------------------------------
// Problem constants
// ---------------------------------------------------------------------------
#define BG   2048      // graphs
#define NN_  65536     // nodes
#define NE_  131072    // edges
#define DN_  256       // node dim
#define DE_  128       // edge dim

// ---------------------------------------------------------------------------
// Scratch (device globals; allocation-free)
// ---------------------------------------------------------------------------
__device__ __align__(256) float g_h_n[BG * DN_];
__device__ __align__(256) float g_c_n[BG * DN_];
__device__ __align__(256) float g_gates_n[BG * 4 * DN_];
__device__ __align__(256) float g_h_e[BG * DE_];
__device__ __align__(256) float g_c_e[BG * DE_];
__device__ __align__(256) float g_gates_e[BG * 4 * DE_];

// split activations (bf16 hi/lo)
__device__ __align__(256) __nv_bfloat16 g_qs_n_hi[BG * 512];
__device__ __align__(256) __nv_bfloat16 g_qs_n_lo[BG * 512];
__device__ __align__(256) __nv_bfloat16 g_qs_e_hi[BG * 256];
__device__ __align__(256) __nv_bfloat16 g_qs_e_lo[BG * 256];
__device__ __align__(256) __nv_bfloat16 g_qcat_hi[BG * 768];
__device__ __align__(256) __nv_bfloat16 g_qcat_lo[BG * 768];
__device__ __align__(256) __nv_bfloat16 g_t1_hi[BG * 512];
__device__ __align__(256) __nv_bfloat16 g_t1_lo[BG * 512];
__device__ __align__(256) __nv_bfloat16 g_t2_hi[BG * 2048];
__device__ __align__(256) __nv_bfloat16 g_t2_lo[BG * 2048];
__device__ __align__(256) __nv_bfloat16 g_t3_hi[BG * 512];
__device__ __align__(256) __nv_bfloat16 g_t3_lo[BG * 512];
__device__ __align__(256) float g_t4[BG * 512];

// split weights (bf16 hi/lo, [N, K] K-major for all)
__device__ __align__(256) __nv_bfloat16 g_Wn_hi[1024 * 512];
__device__ __align__(256) __nv_bfloat16 g_Wn_lo[1024 * 512];
__device__ __align__(256) __nv_bfloat16 g_We_hi[512 * 256];
__device__ __align__(256) __nv_bfloat16 g_We_lo[512 * 256];
__device__ __align__(256) __nv_bfloat16 g_Wd1_hi[512 * 768];
__device__ __align__(256) __nv_bfloat16 g_Wd1_lo[512 * 768];
__device__ __align__(256) __nv_bfloat16 g_Wd2_hi[2048 * 512];
__device__ __align__(256) __nv_bfloat16 g_Wd2_lo[2048 * 512];
__device__ __align__(256) __nv_bfloat16 g_Wf1_hi[512 * 2048];
__device__ __align__(256) __nv_bfloat16 g_Wf1_lo[512 * 2048];
__device__ __align__(256) __nv_bfloat16 g_Wf2_hi[512 * 512];
__device__ __align__(256) __nv_bfloat16 g_Wf2_lo[512 * 512];

__device__ float g_score[NE_];
__device__ int   g_off_n[BG + 1];
__device__ int   g_off_e[BG + 1];

// ---------------------------------------------------------------------------
// helpers
// ---------------------------------------------------------------------------
__device__ __forceinline__ uint32_t smem_u32(const void* p) {
    return (uint32_t)__cvta_generic_to_shared(p);
}
__device__ __forceinline__ void split_f32(float v, __nv_bfloat16& hi, __nv_bfloat16& lo) {
    hi = __float2bfloat16(v);
    lo = __float2bfloat16(v - __bfloat162float(hi));
}

#define LDM_X4(R, addr) \
    asm volatile("ldmatrix.sync.aligned.m8n8.x4.shared.b16 {%0,%1,%2,%3}, [%4];" \
                 : "=r"((R)[0]), "=r"((R)[1]), "=r"((R)[2]), "=r"((R)[3]) : "r"(addr))
#define MMA16816(D, A, B0, B1) \
    asm volatile("mma.sync.aligned.m16n8k16.row.col.f32.bf16.bf16.f32 " \
                 "{%0,%1,%2,%3}, {%4,%5,%6,%7}, {%8,%9}, {%0,%1,%2,%3};" \
                 : "+f"((D)[0]), "+f"((D)[1]), "+f"((D)[2]), "+f"((D)[3]) \
                 : "r"((A)[0]), "r"((A)[1]), "r"((A)[2]), "r"((A)[3]), \
                   "r"(B0), "r"(B1))

// ---------------------------------------------------------------------------
// mma.sync bf16 GEMM:  C[M,N] = epilogue( A[M,K] @ W[N,K]^T + bias )
// A,W given as bf16 hi/lo splits; 3-term compensation (hh + hl + lh), fp32 acc.
// B tile is stored [N rows, K cols] (K-major). For mma row.col, the B fragment
// is produced by PLAIN ldmatrix (no .trans): thread i then holds
// M[i/4][2*(i%4)] = B[n=i/4][k=2*(i%4)], exactly the required col-major
// fragment. (.trans would swap n/k inside each 8x8 block — the round-5 bug.)
// MODE: 0 = +bias1+bias2 ; 1 = +bias1, relu ; 2 = +bias1
// OUTSPLIT: 1 -> write bf16 hi/lo ; 0 -> write fp32
// grid = (N/64, M/128), 256 threads (8 warps, 4x2 of 32x32 tiles), BK=64.
// ---------------------------------------------------------------------------
#define LDT 72                      // padded row stride in bf16 (36 words; conflict-free)
#define SM_A_BYTES (128 * LDT * 2)  // 18432 per A buffer
#define SM_B_BYTES (64 * LDT * 2)   //  9216 per B buffer
#define GEMM_DYN_SMEM (2 * SM_A_BYTES + 2 * SM_B_BYTES)   // 55296

template <int MODE, int OUTSPLIT>
__global__ __launch_bounds__(256) void mma_gemm(
    const __nv_bfloat16* __restrict__ Ahi, const __nv_bfloat16* __restrict__ Alo,
    const __nv_bfloat16* __restrict__ Bhi, const __nv_bfloat16* __restrict__ Blo,
    const float* __restrict__ bias1, const float* __restrict__ bias2,
    float* __restrict__ Cf, __nv_bfloat16* __restrict__ Chi,
    __nv_bfloat16* __restrict__ Clo, int N, int K)
{
    extern __shared__ char smem[];
    char* sAh = smem;
    char* sAl = smem + SM_A_BYTES;
    char* sBh = smem + 2 * SM_A_BYTES;
    char* sBl = smem + 2 * SM_A_BYTES + SM_B_BYTES;
    uint32_t uAh = smem_u32(sAh), uAl = smem_u32(sAl);
    uint32_t uBh = smem_u32(sBh), uBl = smem_u32(sBl);

    int tid = threadIdx.x, lane = tid & 31, wid = tid >> 5;
    int wm = wid & 3, wn = wid >> 2;           // 4 x 2 warp grid
    int row0 = blockIdx.y * 128, col0 = blockIdx.x * 64;

    float acc[2][4][4];
    #pragma unroll
    for (int i = 0; i < 2; i++)
        #pragma unroll
        for (int j = 0; j < 4; j++)
            #pragma unroll
            for (int t = 0; t < 4; t++) acc[i][j][t] = 0.f;

    // ldmatrix source rows/cols (fixed per thread)
    int rA = (lane & 15);                       // + wm*32 + mi*16
    int cA8 = ((lane >> 4) << 3);               // + k16*16
    int rB = ((lane >> 4) << 3) + (lane & 7);   // + wn*32 + nj*16  (n-row)
    int cB8 = (((lane >> 3) & 1) << 3);         // + k16*16         (k-col)

    int nch = K >> 6;
    for (int ch = 0; ch < nch; ch++) {
        __syncthreads();
        // ---- load A tile (128 x 64 bf16, hi+lo) ----
        {
            const __nv_bfloat16* pH = Ahi + (size_t)row0 * K + ch * 64;
            const __nv_bfloat16* pL = Alo + (size_t)row0 * K + ch * 64;
            #pragma unroll
            for (int p = 0; p < 4; p++) {
                int u = tid + p * 256;
                int r = u >> 3, s = u & 7;
                size_t go = (size_t)r * K + s * 8;
                uint32_t so = (uint32_t)(r * LDT + s * 8) * 2;
                *(uint4*)(sAh + so) = *(const uint4*)(pH + go);
                *(uint4*)(sAl + so) = *(const uint4*)(pL + go);
            }
        }
        // ---- load B tile (64 x 64 bf16, hi+lo) ----
        {
            const __nv_bfloat16* pH = Bhi + (size_t)col0 * K + ch * 64;
            const __nv_bfloat16* pL = Blo + (size_t)col0 * K + ch * 64;
            #pragma unroll
            for (int p = 0; p < 2; p++) {
                int u = tid + p * 256;
                int r = u >> 3, s = u & 7;
                size_t go = (size_t)r * K + s * 8;
                uint32_t so = (uint32_t)(r * LDT + s * 8) * 2;
                *(uint4*)(sBh + so) = *(const uint4*)(pH + go);
                *(uint4*)(sBl + so) = *(const uint4*)(pL + go);
            }
        }
        __syncthreads();

        #pragma unroll
        for (int k16 = 0; k16 < 4; k16++) {
            uint32_t ah[2][4], al[2][4], bh[2][4], bl[2][4];
            #pragma unroll
            for (int mi = 0; mi < 2; mi++) {
                uint32_t off = (uint32_t)((wm * 32 + mi * 16 + rA) * LDT
                                          + k16 * 16 + cA8) * 2;
                LDM_X4(ah[mi], uAh + off);
                LDM_X4(al[mi], uAl + off);
            }
            #pragma unroll
            for (int nj = 0; nj < 2; nj++) {
                uint32_t off = (uint32_t)((wn * 32 + nj * 16 + rB) * LDT
                                          + k16 * 16 + cB8) * 2;
                LDM_X4(bh[nj], uBh + off);   // NO .trans: [N,K] storage
                LDM_X4(bl[nj], uBl + off);
            }
            #pragma unroll
            for (int mi = 0; mi < 2; mi++) {
                #pragma unroll
                for (int na = 0; na < 4; na++) {
                    int nj = na >> 1, pr = (na & 1) * 2;
                    MMA16816(acc[mi][na], ah[mi], bh[nj][pr], bh[nj][pr + 1]);
                    MMA16816(acc[mi][na], ah[mi], bl[nj][pr], bl[nj][pr + 1]);
                    MMA16816(acc[mi][na], al[mi], bh[nj][pr], bh[nj][pr + 1]);
                }
            }
        }
    }

    // ---- epilogue ----
    #pragma unroll
    for (int mi = 0; mi < 2; mi++) {
        int r_lo = row0 + wm * 32 + mi * 16 + (lane >> 2);
        #pragma unroll
        for (int na = 0; na < 4; na++) {
            int c = col0 + wn * 32 + na * 8 + (lane & 3) * 2;
            #pragma unroll
            for (int half = 0; half < 2; half++) {
                int r = r_lo + half * 8;
                float v0 = acc[mi][na][half * 2 + 0];
                float v1 = acc[mi][na][half * 2 + 1];
                if (MODE == 0) {
                    v0 += bias1[c] + bias2[c];
                    v1 += bias1[c + 1] + bias2[c + 1];
                } else {
                    v0 += bias1[c];
                    v1 += bias1[c + 1];
                }
                if (MODE == 1) { v0 = fmaxf(v0, 0.f); v1 = fmaxf(v1, 0.f); }
                if (OUTSPLIT) {
                    __nv_bfloat16 h0, l0, h1, l1;
                    split_f32(v0, h0, l0);
                    split_f32(v1, h1, l1);
                    __nv_bfloat162 hp; hp.x = h0; hp.y = h1;
                    __nv_bfloat162 lp; lp.x = l0; lp.y = l1;
                    *(__nv_bfloat162*)(Chi + (size_t)r * N + c) = hp;
                    *(__nv_bfloat162*)(Clo + (size_t)r * N + c) = lp;
                } else {
                    float2 fv; fv.x = v0; fv.y = v1;
                    *(float2*)(Cf + (size_t)r * N + c) = fv;
                }
            }
        }
    }
}

// ---------------------------------------------------------------------------
// Prep / pointwise kernels
// ---------------------------------------------------------------------------
__global__ void zero_c_kernel() {
    int i = blockIdx.x * 256 + threadIdx.x;
    if (i < BG * DN_) g_c_n[i] = 0.f;
    if (i < BG * DE_) g_c_e[i] = 0.f;
}

__global__ void segoff_kernel(const int* __restrict__ seg, int M, int* __restrict__ off) {
    int b = blockIdx.x * blockDim.x + threadIdx.x;
    if (b > BG) return;
    int lo = 0, hi = M;
    while (lo < hi) {
        int mid = (lo + hi) >> 1;
        if (seg[mid] < b) lo = mid + 1; else hi = mid;
    }
    off[b] = lo;
}

// LSTM combined weight: Wc = Wih + [Whh | 0], split to bf16 hi/lo. out [4D, 2D]
__global__ void wcomb_split_kernel(const float* __restrict__ Wih,
                                   const float* __restrict__ Whh,
                                   __nv_bfloat16* __restrict__ hi,
                                   __nv_bfloat16* __restrict__ lo, int D) {
    int i = blockIdx.x * 256 + threadIdx.x;
    int total = 4 * D * 2 * D;
    if (i >= total) return;
    int r = i / (2 * D), c = i - r * 2 * D;
    float v = Wih[i];
    if (c < D) v += Whh[(size_t)r * D + c];
    __nv_bfloat16 h, l;
    split_f32(v, h, l);
    hi[i] = h; lo[i] = l;
}

// transpose [K,N] -> [N,K] and split
__global__ void wtrans_split_kernel(const float* __restrict__ W,
                                    __nv_bfloat16* __restrict__ hi,
                                    __nv_bfloat16* __restrict__ lo, int K, int N) {
    __shared__ float t[32][33];
    int kb = blockIdx.y * 32, nb = blockIdx.x * 32;
    int tx = threadIdx.x, ty = threadIdx.y;
    #pragma unroll
    for (int i = 0; i < 4; i++)
        t[ty + i * 8][tx] = W[(size_t)(kb + ty + i * 8) * N + nb + tx];
    __syncthreads();
    #pragma unroll
    for (int i = 0; i < 4; i++) {
        float v = t[tx][ty + i * 8];
        __nv_bfloat16 h, l;
        split_f32(v, h, l);
        size_t o = (size_t)(nb + ty + i * 8) * K + kb + tx;
        hi[o] = h; lo[o] = l;
    }
}

// iter-0 gates: bih + bhh broadcast
__global__ void gates_bias_kernel(const float* __restrict__ bih,
                                  const float* __restrict__ bhh,
                                  float* __restrict__ gates, int G) {
    int i = blockIdx.x * 256 + threadIdx.x;
    if (i >= BG * G) return;
    int j = i % G;
    gates[i] = bih[j] + bhh[j];
}

__device__ __forceinline__ float sigmoidf_(float x) { return 1.f / (1.f + expf(-x)); }

// LSTM pointwise: h,c update; write q (=h) into split qstar[:, :D]
__global__ void lstm_pw_kernel(const float* __restrict__ gates,
                               float* __restrict__ h, float* __restrict__ c,
                               __nv_bfloat16* __restrict__ qhi,
                               __nv_bfloat16* __restrict__ qlo, int D) {
    int idx = blockIdx.x * 256 + threadIdx.x;
    if (idx >= BG * D) return;
    int b = idx / D, d = idx - b * D;
    const float* gr = gates + (size_t)b * 4 * D;
    float gi = gr[d], gf = gr[D + d], gg = gr[2 * D + d], go = gr[3 * D + d];
    float cn = sigmoidf_(gf) * c[idx] + sigmoidf_(gi) * tanhf(gg);
    float hn = sigmoidf_(go) * tanhf(cn);
    c[idx] = cn;
    h[idx] = hn;
    __nv_bfloat16 hh, ll;
    split_f32(hn, hh, ll);
    qhi[(size_t)b * 2 * D + d] = hh;
    qlo[(size_t)b * 2 * D + d] = ll;
}

// ---------------------------------------------------------------------------
// Set2Set attention (block per segment, 2 passes); readout -> split qstar[:, D:]
// ---------------------------------------------------------------------------
template <int D>
__global__ __launch_bounds__(256) void s2s_attn_kernel(
    const float* __restrict__ feat, const int* __restrict__ segoff,
    const float* __restrict__ h,
    __nv_bfloat16* __restrict__ qhi, __nv_bfloat16* __restrict__ qlo,
    float* __restrict__ scorebuf) {
    int b = blockIdx.x;
    int tid = threadIdx.x, lane = tid & 31, w = tid >> 5;
    int start = segoff[b], end = segoff[b + 1];

    __shared__ float q[D];
    __shared__ float acc[8][D];
    __shared__ float red[8];

    for (int i = tid; i < D; i += 256) q[i] = h[(size_t)b * D + i];
    for (int i = tid; i < 8 * D; i += 256) (&acc[0][0])[i] = 0.f;
    __syncthreads();

    float wmax = -INFINITY;
    for (int m = start + w; m < end; m += 8) {
        const float* fr = feat + (size_t)m * D;
        float s = 0.f;
        #pragma unroll
        for (int k = lane; k < D; k += 32) s += fr[k] * q[k];
        #pragma unroll
        for (int o = 16; o; o >>= 1) s += __shfl_xor_sync(0xffffffffu, s, o);
        if (lane == 0) scorebuf[m] = s;
        wmax = fmaxf(wmax, s);
    }
    if (lane == 0) red[w] = wmax;
    __syncthreads();
    float smax = -INFINITY;
    #pragma unroll
    for (int i = 0; i < 8; i++) smax = fmaxf(smax, red[i]);
    __syncthreads();

    float sumw = 0.f;
    for (int m = start + w; m < end; m += 8) {
        const float* fr = feat + (size_t)m * D;
        float wv = expf(scorebuf[m] - smax);
        if (lane == 0) sumw += wv;
        #pragma unroll
        for (int k = lane; k < D; k += 32) acc[w][k] += wv * fr[k];
    }
    if (lane == 0) red[w] = sumw;
    __syncthreads();
    float tot = 0.f;
    #pragma unroll
    for (int i = 0; i < 8; i++) tot += red[i];
    float inv = (tot > 0.f) ? (1.f / tot) : 0.f;

    for (int k = tid; k < D; k += 256) {
        float r = 0.f;
        #pragma unroll
        for (int i = 0; i < 8; i++) r += acc[i][k];
        float v = r * inv;
        __nv_bfloat16 hh, ll;
        split_f32(v, hh, ll);
        qhi[(size_t)b * 2 * D + D + k] = hh;
        qlo[(size_t)b * 2 * D + D + k] = ll;
    }
}

// concat qstar_n (512) + qstar_e (256) -> qcat (768), hi & lo
__global__ void concat_kernel() {
    int i = blockIdx.x * 256 + threadIdx.x;
    if (i >= BG * 768) return;
    int b = i / 768, j = i - b * 768;
    if (j < 512) {
        size_t s = (size_t)b * 512 + j;
        g_qcat_hi[i] = g_qs_n_hi[s];
        g_qcat_lo[i] = g_qs_n_lo[s];
    } else {
        size_t s = (size_t)b * 256 + (j - 512);
        g_qcat_hi[i] = g_qs_e_hi[s];
        g_qcat_lo[i] = g_qs_e_lo[s];
    }
}

// final GEMV: pred[b] = t4[b,:] . Wf3 + bf3
__global__ void gemv_final_kernel(const float* __restrict__ A,
                                  const float* __restrict__ w,
                                  const float* __restrict__ bias,
                                  float* __restrict__ out, int K) {
    int b = blockIdx.x * 8 + (threadIdx.x >> 5);
    int lane = threadIdx.x & 31;
    if (b >= BG) return;
    const float* ar = A + (size_t)b * K;
    float s = 0.f;
    for (int k = lane; k < K; k += 32) s += ar[k] * w[k];
    #pragma unroll
    for (int o = 16; o; o >>= 1) s += __shfl_xor_sync(0xffffffffu, s, o);
    if (lane == 0) out[b] = s + bias[0];
}

// ---------------------------------------------------------------------------
// Host orchestration
// ---------------------------------------------------------------------------
template <typename T>
static T* dsym(const void* s) {
    void* p = nullptr;
    cudaGetSymbolAddress(&p, s);
    return (T*)p;
}

extern "C" void kernel_launch(void* const* d_in, const int* in_sizes, int n_in,
                              void* d_out, int out_size) {
    const float* node_feat = (const float*)d_in[0];
    const float* edge_feat = (const float*)d_in[1];
    const int*   node_seg  = (const int*)d_in[2];
    const int*   edge_seg  = (const int*)d_in[3];
    const float* Wih_n = (const float*)d_in[4];
    const float* Whh_n = (const float*)d_in[5];
    const float* bih_n = (const float*)d_in[6];
    const float* bhh_n = (const float*)d_in[7];
    const float* Wih_e = (const float*)d_in[8];
    const float* Whh_e = (const float*)d_in[9];
    const float* bih_e = (const float*)d_in[10];
    const float* bhh_e = (const float*)d_in[11];
    const float* Wd1 = (const float*)d_in[12];
    const float* bd1 = (const float*)d_in[13];
    const float* Wd2 = (const float*)d_in[14];
    const float* bd2 = (const float*)d_in[15];
    const float* Wf1 = (const float*)d_in[16];
    const float* bf1 = (const float*)d_in[17];
    const float* Wf2 = (const float*)d_in[18];
    const float* bf2 = (const float*)d_in[19];
    const float* Wf3 = (const float*)d_in[20];
    const float* bf3 = (const float*)d_in[21];
    float* out = (float*)d_out;

    cudaFuncSetAttribute(mma_gemm<0, 0>, cudaFuncAttributeMaxDynamicSharedMemorySize, GEMM_DYN_SMEM);
    cudaFuncSetAttribute(mma_gemm<1, 1>, cudaFuncAttributeMaxDynamicSharedMemorySize, GEMM_DYN_SMEM);
    cudaFuncSetAttribute(mma_gemm<2, 1>, cudaFuncAttributeMaxDynamicSharedMemorySize, GEMM_DYN_SMEM);
    cudaFuncSetAttribute(mma_gemm<1, 0>, cudaFuncAttributeMaxDynamicSharedMemorySize, GEMM_DYN_SMEM);

    float* h_n = dsym<float>(g_h_n);   float* c_n = dsym<float>(g_c_n);
    float* ga_n = dsym<float>(g_gates_n);
    float* h_e = dsym<float>(g_h_e);   float* c_e = dsym<float>(g_c_e);
    float* ga_e = dsym<float>(g_gates_e);
    __nv_bfloat16* qsn_h = dsym<__nv_bfloat16>(g_qs_n_hi);
    __nv_bfloat16* qsn_l = dsym<__nv_bfloat16>(g_qs_n_lo);
    __nv_bfloat16* qse_h = dsym<__nv_bfloat16>(g_qs_e_hi);
    __nv_bfloat16* qse_l = dsym<__nv_bfloat16>(g_qs_e_lo);
    __nv_bfloat16* qc_h = dsym<__nv_bfloat16>(g_qcat_hi);
    __nv_bfloat16* qc_l = dsym<__nv_bfloat16>(g_qcat_lo);
    __nv_bfloat16* t1h = dsym<__nv_bfloat16>(g_t1_hi);
    __nv_bfloat16* t1l = dsym<__nv_bfloat16>(g_t1_lo);
    __nv_bfloat16* t2h = dsym<__nv_bfloat16>(g_t2_hi);
    __nv_bfloat16* t2l = dsym<__nv_bfloat16>(g_t2_lo);
    __nv_bfloat16* t3h = dsym<__nv_bfloat16>(g_t3_hi);
    __nv_bfloat16* t3l = dsym<__nv_bfloat16>(g_t3_lo);
    float* t4 = dsym<float>(g_t4);
    __nv_bfloat16* Wnh = dsym<__nv_bfloat16>(g_Wn_hi);
    __nv_bfloat16* Wnl = dsym<__nv_bfloat16>(g_Wn_lo);
    __nv_bfloat16* Weh = dsym<__nv_bfloat16>(g_We_hi);
    __nv_bfloat16* Wel = dsym<__nv_bfloat16>(g_We_lo);
    __nv_bfloat16* Wd1h = dsym<__nv_bfloat16>(g_Wd1_hi);
    __nv_bfloat16* Wd1l = dsym<__nv_bfloat16>(g_Wd1_lo);
    __nv_bfloat16* Wd2h = dsym<__nv_bfloat16>(g_Wd2_hi);
    __nv_bfloat16* Wd2l = dsym<__nv_bfloat16>(g_Wd2_lo);
    __nv_bfloat16* Wf1h = dsym<__nv_bfloat16>(g_Wf1_hi);
    __nv_bfloat16* Wf1l = dsym<__nv_bfloat16>(g_Wf1_lo);
    __nv_bfloat16* Wf2h = dsym<__nv_bfloat16>(g_Wf2_hi);
    __nv_bfloat16* Wf2l = dsym<__nv_bfloat16>(g_Wf2_lo);
    float* score = dsym<float>(g_score);
    int* off_n = dsym<int>(g_off_n);
    int* off_e = dsym<int>(g_off_e);

    // ---- prep ----
    zero_c_kernel<<<(BG * DN_ + 255) / 256, 256>>>();
    segoff_kernel<<<(BG + 256) / 256, 256>>>(node_seg, NN_, off_n);
    segoff_kernel<<<(BG + 256) / 256, 256>>>(edge_seg, NE_, off_e);
    wcomb_split_kernel<<<(1024 * 512 + 255) / 256, 256>>>(Wih_n, Whh_n, Wnh, Wnl, DN_);
    wcomb_split_kernel<<<(512 * 256 + 255) / 256, 256>>>(Wih_e, Whh_e, Weh, Wel, DE_);
    {
        dim3 t(32, 8);
        wtrans_split_kernel<<<dim3(512 / 32, 768 / 32), t>>>(Wd1, Wd1h, Wd1l, 768, 512);
        wtrans_split_kernel<<<dim3(2048 / 32, 512 / 32), t>>>(Wd2, Wd2h, Wd2l, 512, 2048);
        wtrans_split_kernel<<<dim3(512 / 32, 2048 / 32), t>>>(Wf1, Wf1h, Wf1l, 2048, 512);
        wtrans_split_kernel<<<dim3(512 / 32, 512 / 32), t>>>(Wf2, Wf2h, Wf2l, 512, 512);
    }

    // ---- node Set2Set (D=256, 2D=512, gates 4D=1024) ----
    {
        dim3 grid(1024 / 64, BG / 128);
        for (int it = 0; it < 6; it++) {
            if (it == 0) {
                gates_bias_kernel<<<(BG * 1024 + 255) / 256, 256>>>(bih_n, bhh_n, ga_n, 1024);
            } else {
                mma_gemm<0, 0><<<grid, 256, GEMM_DYN_SMEM>>>(
                    qsn_h, qsn_l, Wnh, Wnl, bih_n, bhh_n, ga_n, nullptr, nullptr, 1024, 512);
            }
            lstm_pw_kernel<<<(BG * DN_ + 255) / 256, 256>>>(ga_n, h_n, c_n, qsn_h, qsn_l, DN_);
            s2s_attn_kernel<DN_><<<BG, 256>>>(node_feat, off_n, h_n, qsn_h, qsn_l, score);
        }
    }

    // ---- edge Set2Set (D=128, 2D=256, gates 4D=512) ----
    {
        dim3 grid(512 / 64, BG / 128);
        for (int it = 0; it < 6; it++) {
            if (it == 0) {
                gates_bias_kernel<<<(BG * 512 + 255) / 256, 256>>>(bih_e, bhh_e, ga_e, 512);
            } else {
                mma_gemm<0, 0><<<grid, 256, GEMM_DYN_SMEM>>>(
                    qse_h, qse_l, Weh, Wel, bih_e, bhh_e, ga_e, nullptr, nullptr, 512, 256);
            }
            lstm_pw_kernel<<<(BG * DE_ + 255) / 256, 256>>>(ga_e, h_e, c_e, qse_h, qse_l, DE_);
            s2s_attn_kernel<DE_><<<BG, 256>>>(edge_feat, off_e, h_e, qse_h, qse_l, score);
        }
    }

    // ---- decode + regression FFN ----
    concat_kernel<<<(BG * 768 + 255) / 256, 256>>>();
    {
        dim3 g1(512 / 64, BG / 128);
        dim3 g2(2048 / 64, BG / 128);
        mma_gemm<1, 1><<<g1, 256, GEMM_DYN_SMEM>>>(
            qc_h, qc_l, Wd1h, Wd1l, bd1, nullptr, nullptr, t1h, t1l, 512, 768);
        mma_gemm<2, 1><<<g2, 256, GEMM_DYN_SMEM>>>(
            t1h, t1l, Wd2h, Wd2l, bd2, nullptr, nullptr, t2h, t2l, 2048, 512);
        mma_gemm<1, 1><<<g1, 256, GEMM_DYN_SMEM>>>(
            t2h, t2l, Wf1h, Wf1l, bf1, nullptr, nullptr, t3h, t3l, 512, 2048);
        mma_gemm<1, 0><<<g1, 256, GEMM_DYN_SMEM>>>(
            t3h, t3l, Wf2h, Wf2l, bf2, nullptr, t4, nullptr, nullptr, 512, 512);
    }
    gemv_final_kernel<<<BG / 8, 256>>>(t4, Wf3, bf3, out, 512);
}